// round 6
// baseline (speedup 1.0000x reference)
#include <cuda_runtime.h>
#include <cstdint>

#define TC      25
#define HU      64      // hidden units
#define G4      256     // 4*H
#define SPB     32      // sequences per block
#define NTHR    256
#define NSEQ    32768

// Precomputed input projection table: EWb[v][j] = sum_d E[v][d]*W[d][j] + b[j]
__device__ float g_EWb[128 * G4];

__global__ void ewb_kernel(const float* __restrict__ E,
                           const float* __restrict__ W,
                           const float* __restrict__ b) {
    int v = blockIdx.x;       // vocab row 0..127
    int j = threadIdx.x;      // gate column 0..255
    float acc = b[j];
#pragma unroll
    for (int d = 0; d < 32; d++)
        acc = fmaf(E[v * 32 + d], W[d * G4 + j], acc);
    g_EWb[v * G4 + j] = acc;
}

__device__ __forceinline__ float fast_ex2(float x) {
    float y; asm("ex2.approx.f32 %0, %1;" : "=f"(y) : "f"(x)); return y;
}
__device__ __forceinline__ float fast_rcp(float x) {
    float y; asm("rcp.approx.f32 %0, %1;" : "=f"(y) : "f"(x)); return y;
}
// sigmoid(x) = 1 / (1 + e^-x)
__device__ __forceinline__ float sigmoid_(float x) {
    float e = fast_ex2(-1.4426950408889634f * x);
    return fast_rcp(1.0f + e);
}
// tanh(x) = 1 - 2/(e^{2x} + 1)
__device__ __forceinline__ float tanh_(float x) {
    float e = fast_ex2(2.8853900817779268f * x);
    return fmaf(-2.0f, fast_rcp(1.0f + e), 1.0f);
}

__global__ void __launch_bounds__(NTHR, 2)
lstm_kernel(const int* __restrict__ chars,
            const float* __restrict__ U,
            float* __restrict__ out) {
    __shared__ float h_sm[SPB * HU];      // 8 KB   current hidden state
    __shared__ float z_sm[SPB * G4];      // 32 KB  gate pre-activations
    __shared__ int   ch_sm[SPB * TC];     // 3.2 KB char ids for this block

    const int t    = threadIdx.x;         // GEMM phase: column j of z
    const int seq0 = blockIdx.x * SPB;

    // U column t resident in registers for the whole kernel.
    float U_reg[HU];
#pragma unroll
    for (int k = 0; k < HU; k++) U_reg[k] = U[k * G4 + t];

    // Stage chars and zero h.
    for (int i = t; i < SPB * TC; i += NTHR) ch_sm[i] = chars[seq0 * TC + i];
    for (int i = t; i < SPB * HU; i += NTHR) h_sm[i] = 0.0f;

    // Gate-phase ownership: thread t updates (s, u) pairs with
    // u = t & 63, s = (t >> 6) + 4*r for r = 0..7. c-state in registers.
    const int gu  = t & 63;
    const int gs0 = t >> 6;
    float c_reg[8];
#pragma unroll
    for (int r = 0; r < 8; r++) c_reg[r] = 0.0f;

    __syncthreads();

    for (int step = 0; step < TC; step++) {
        // ---------------- GEMM phase: z[s][t] = EWb[ch[s][step]][t] + h[s]@U[:,t]
#pragma unroll 1
        for (int s0 = 0; s0 < SPB; s0 += 4) {
            float a0 = g_EWb[ch_sm[(s0 + 0) * TC + step] * G4 + t];
            float a1 = g_EWb[ch_sm[(s0 + 1) * TC + step] * G4 + t];
            float a2 = g_EWb[ch_sm[(s0 + 2) * TC + step] * G4 + t];
            float a3 = g_EWb[ch_sm[(s0 + 3) * TC + step] * G4 + t];
#pragma unroll
            for (int k = 0; k < HU; k += 4) {
                float4 h0 = *(const float4*)&h_sm[(s0 + 0) * HU + k];
                float4 h1 = *(const float4*)&h_sm[(s0 + 1) * HU + k];
                float4 h2 = *(const float4*)&h_sm[(s0 + 2) * HU + k];
                float4 h3 = *(const float4*)&h_sm[(s0 + 3) * HU + k];
                a0 = fmaf(h0.x, U_reg[k+0], a0); a0 = fmaf(h0.y, U_reg[k+1], a0);
                a0 = fmaf(h0.z, U_reg[k+2], a0); a0 = fmaf(h0.w, U_reg[k+3], a0);
                a1 = fmaf(h1.x, U_reg[k+0], a1); a1 = fmaf(h1.y, U_reg[k+1], a1);
                a1 = fmaf(h1.z, U_reg[k+2], a1); a1 = fmaf(h1.w, U_reg[k+3], a1);
                a2 = fmaf(h2.x, U_reg[k+0], a2); a2 = fmaf(h2.y, U_reg[k+1], a2);
                a2 = fmaf(h2.z, U_reg[k+2], a2); a2 = fmaf(h2.w, U_reg[k+3], a2);
                a3 = fmaf(h3.x, U_reg[k+0], a3); a3 = fmaf(h3.y, U_reg[k+1], a3);
                a3 = fmaf(h3.z, U_reg[k+2], a3); a3 = fmaf(h3.w, U_reg[k+3], a3);
            }
            z_sm[(s0 + 0) * G4 + t] = a0;
            z_sm[(s0 + 1) * G4 + t] = a1;
            z_sm[(s0 + 2) * G4 + t] = a2;
            z_sm[(s0 + 3) * G4 + t] = a3;
        }
        __syncthreads();

        // ---------------- Gate phase: LSTM cell update (Keras order i,f,g,o)
#pragma unroll
        for (int r = 0; r < 8; r++) {
            int s = gs0 + 4 * r;
            float zi = z_sm[s * G4 +   0 + gu];
            float zf = z_sm[s * G4 +  64 + gu];
            float zg = z_sm[s * G4 + 128 + gu];
            float zo = z_sm[s * G4 + 192 + gu];
            float ig = sigmoid_(zi);
            float fg = sigmoid_(zf);
            float gg = tanh_(zg);
            float og = sigmoid_(zo);
            float c  = fmaf(fg, c_reg[r], ig * gg);
            c_reg[r] = c;
            float h  = og * tanh_(c);
            if (step == TC - 1)
                out[(seq0 + s) * HU + gu] = h;
            else
                h_sm[s * HU + gu] = h;
        }
        __syncthreads();
    }
}

extern "C" void kernel_launch(void* const* d_in, const int* in_sizes, int n_in,
                              void* d_out, int out_size) {
    const int*   chars = (const int*)d_in[0];
    const float* E     = (const float*)d_in[1];
    const float* W     = (const float*)d_in[2];
    const float* U     = (const float*)d_in[3];
    const float* b     = (const float*)d_in[4];
    float* out = (float*)d_out;

    ewb_kernel<<<128, 256>>>(E, W, b);
    lstm_kernel<<<NSEQ / SPB, NTHR>>>(chars, U, out);
}

// round 8
// speedup vs baseline: 1.5944x; 1.5944x over previous
#include <cuda_runtime.h>
#include <cstdint>

#define TC   25
#define HU   64
#define G4   256
#define SPB  32                  // sequences per CTA
#define NTHR 256
#define NSEQ 32768
#define NBLK (NSEQ / SPB)        // 1024 CTAs

// dynamic smem layout
#define OFF_UG 0u                // Ug[k][u] float4 = 64*64*16 = 64 KB
#define OFF_H  65536u            // 2 x h buffer, k-major [64][40] floats
#define HBUF   10240u            // 64 * 160 bytes
#define OFF_CH 86016u            // chars [32][25] int = 3200 B
#define SMEM_TOTAL 89216u
#define HSTRIDE 160              // bytes per k-row (40 floats, pad kills STS conflicts)

typedef unsigned long long ull;

__device__ float g_EWb[128 * G4];   // EWb[v][j] = (E@W)[v][j] + b[j]

__global__ void ewb_kernel(const float* __restrict__ E,
                           const float* __restrict__ W,
                           const float* __restrict__ b) {
    int v = blockIdx.x, j = threadIdx.x;
    float acc = b[j];
#pragma unroll
    for (int d = 0; d < 32; d++)
        acc = fmaf(E[v * 32 + d], W[d * G4 + j], acc);
    g_EWb[v * G4 + j] = acc;
}

// ---------------- packed f32x2 helpers (sm_100 family, ptxas-safe) ----------
__device__ __forceinline__ ull ffma2(ull a, ull b, ull c) {
    ull d;
    asm("fma.rn.f32x2 %0, %1, %2, %3;" : "=l"(d) : "l"(a), "l"(b), "l"(c));
    return d;
}
__device__ __forceinline__ ull dup2(float x) {
    ull d;
    asm("mov.b64 %0, {%1, %1};" : "=l"(d) : "f"(x));
    return d;
}
__device__ __forceinline__ ull pack2(float x, float y) {
    ull d;
    asm("mov.b64 %0, {%1, %2};" : "=l"(d) : "f"(x), "f"(y));
    return d;
}
__device__ __forceinline__ float2 unpack2(ull v) {
    float2 r;
    asm("mov.b64 {%0, %1}, %2;" : "=f"(r.x), "=f"(r.y) : "l"(v));
    return r;
}
__device__ __forceinline__ float fast_ex2(float x) {
    float y; asm("ex2.approx.f32 %0, %1;" : "=f"(y) : "f"(x)); return y;
}
__device__ __forceinline__ float fast_rcp(float x) {
    float y; asm("rcp.approx.f32 %0, %1;" : "=f"(y) : "f"(x)); return y;
}
__device__ __forceinline__ float sigmoid_(float x) {
    return fast_rcp(1.0f + fast_ex2(-1.4426950408889634f * x));
}
__device__ __forceinline__ float tanh_(float x) {
    return fmaf(-2.0f, fast_rcp(1.0f + fast_ex2(2.8853900817779268f * x)), 1.0f);
}

// ---------------------------------------------------------------------------
__global__ void __launch_bounds__(NTHR, 2)
lstm_kernel(const int* __restrict__ chars,
            const float* __restrict__ U,
            float* __restrict__ out) {
    extern __shared__ __align__(16) char smem[];
    const int tid  = threadIdx.x;
    const int u    = tid & 63;          // hidden unit owned by this thread
    const int sgrp = tid >> 6;          // sequence group (0..3), 8 seqs each
    const int S    = sgrp * 8;

    float4* Ug = (float4*)(smem + OFF_UG);   // Ug[k*64 + u] = {Ui,Uf,Ug,Uo}
    int*    ch = (int*)(smem + OFF_CH);

    // ---- init: rearrange U into gate-interleaved float4s ----
    for (int e = tid; e < 64 * 64; e += NTHR) {
        int k = e >> 6, uu = e & 63;
        float4 v;
        v.x = U[k * G4 +       uu];
        v.y = U[k * G4 +  64 + uu];
        v.z = U[k * G4 + 128 + uu];
        v.w = U[k * G4 + 192 + uu];
        Ug[e] = v;
    }
    // zero both h buffers (h0 = 0)
    for (int i = tid; i < (int)(2 * HBUF / 16); i += NTHR)
        ((float4*)(smem + OFF_H))[i] = make_float4(0.f, 0.f, 0.f, 0.f);
    // stage chars
    for (int i = tid; i < SPB * TC; i += NTHR)
        ch[i] = chars[blockIdx.x * SPB * TC + i];
    __syncthreads();

    float c_reg[8];
#pragma unroll
    for (int j = 0; j < 8; j++) c_reg[j] = 0.0f;

    for (int step = 0; step < TC; step++) {
        const int rb = step & 1;

        // ---- accumulator init: z = EWb[char] (packed over seq pairs) ----
        ull acc[16];   // acc[g*4 + p] = {z[S+2p][g*64+u], z[S+2p+1][g*64+u]}
        {
            int vv[8];
#pragma unroll
            for (int i = 0; i < 8; i++) vv[i] = ch[(S + i) * TC + step];
#pragma unroll
            for (int p = 0; p < 4; p++) {
                const float* e0 = g_EWb + vv[2 * p]     * G4 + u;
                const float* e1 = g_EWb + vv[2 * p + 1] * G4 + u;
                acc[0  + p] = pack2(e0[0],   e1[0]);
                acc[4  + p] = pack2(e0[64],  e1[64]);
                acc[8  + p] = pack2(e0[128], e1[128]);
                acc[12 + p] = pack2(e0[192], e1[192]);
            }
        }

        // ---- recurrent GEMM: z += h @ U (f32x2, 16 MACs per k) ----
        const char*   hb  = smem + OFF_H + rb * HBUF + sgrp * 32;
        const float4* ugp = Ug + u;
#pragma unroll 4
        for (int k = 0; k < 64; k++) {
            float4 ug = ugp[k * 64];
            ulonglong2 h01 = *(const ulonglong2*)(hb + k * HSTRIDE);
            ulonglong2 h23 = *(const ulonglong2*)(hb + k * HSTRIDE + 16);
            ull d;
            d = dup2(ug.x);
            acc[0]  = ffma2(h01.x, d, acc[0]);  acc[1]  = ffma2(h01.y, d, acc[1]);
            acc[2]  = ffma2(h23.x, d, acc[2]);  acc[3]  = ffma2(h23.y, d, acc[3]);
            d = dup2(ug.y);
            acc[4]  = ffma2(h01.x, d, acc[4]);  acc[5]  = ffma2(h01.y, d, acc[5]);
            acc[6]  = ffma2(h23.x, d, acc[6]);  acc[7]  = ffma2(h23.y, d, acc[7]);
            d = dup2(ug.z);
            acc[8]  = ffma2(h01.x, d, acc[8]);  acc[9]  = ffma2(h01.y, d, acc[9]);
            acc[10] = ffma2(h23.x, d, acc[10]); acc[11] = ffma2(h23.y, d, acc[11]);
            d = dup2(ug.w);
            acc[12] = ffma2(h01.x, d, acc[12]); acc[13] = ffma2(h01.y, d, acc[13]);
            acc[14] = ffma2(h23.x, d, acc[14]); acc[15] = ffma2(h23.y, d, acc[15]);
        }

        // ---- gates in registers, write h to the other buffer ----
        float* hw = (float*)(smem + OFF_H + (rb ^ 1) * HBUF) + u * 40 + S;
#pragma unroll
        for (int p = 0; p < 4; p++) {
            float2 zi = unpack2(acc[0  + p]);
            float2 zf = unpack2(acc[4  + p]);
            float2 zg = unpack2(acc[8  + p]);
            float2 zo = unpack2(acc[12 + p]);
            {
                float ig = sigmoid_(zi.x), fg = sigmoid_(zf.x);
                float gg = tanh_(zg.x),    og = sigmoid_(zo.x);
                float c  = fmaf(fg, c_reg[2 * p], ig * gg);
                c_reg[2 * p] = c;
                float h  = og * tanh_(c);
                if (step == TC - 1)
                    out[(blockIdx.x * SPB + S + 2 * p) * HU + u] = h;
                else
                    hw[2 * p] = h;
            }
            {
                float ig = sigmoid_(zi.y), fg = sigmoid_(zf.y);
                float gg = tanh_(zg.y),    og = sigmoid_(zo.y);
                float c  = fmaf(fg, c_reg[2 * p + 1], ig * gg);
                c_reg[2 * p + 1] = c;
                float h  = og * tanh_(c);
                if (step == TC - 1)
                    out[(blockIdx.x * SPB + S + 2 * p + 1) * HU + u] = h;
                else
                    hw[2 * p + 1] = h;
            }
        }
        __syncthreads();
    }
}

extern "C" void kernel_launch(void* const* d_in, const int* in_sizes, int n_in,
                              void* d_out, int out_size) {
    const int*   chars = (const int*)d_in[0];
    const float* E     = (const float*)d_in[1];
    const float* W     = (const float*)d_in[2];
    const float* U     = (const float*)d_in[3];
    const float* b     = (const float*)d_in[4];
    float* out = (float*)d_out;

    cudaFuncSetAttribute(lstm_kernel,
                         cudaFuncAttributeMaxDynamicSharedMemorySize, SMEM_TOTAL);
    ewb_kernel<<<128, 256>>>(E, W, b);
    lstm_kernel<<<NBLK, NTHR, SMEM_TOTAL>>>(chars, U, out);
}

// round 9
// speedup vs baseline: 1.6795x; 1.0534x over previous
#include <cuda_runtime.h>
#include <cstdint>

#define TC   25
#define HU   64
#define G4   256
#define SPB  32                  // sequences per CTA
#define NTHR 256
#define NSEQ 32768
#define NBLK (NSEQ / SPB)        // 1024 CTAs

// dynamic smem layout
#define OFF_UG 0u                // Ug[k][u] float4 = 64*64*16 = 64 KB
#define HSTRIDE 144              // bytes per h row (36 floats; 16B-aligned, STS.128 conflict-free)
#define HBUF   (64u * HSTRIDE)   // 9216 B
#define OFF_H  65536u            // 2 x h buffer
#define OFF_CH (OFF_H + 2u * HBUF)        // chars [32][25] int = 3200 B
#define SMEM_TOTAL (OFF_CH + 3200u)

typedef unsigned long long ull;

__device__ float g_EWb[128 * G4];   // EWb[v][j] = (E@W)[v][j] + b[j]

__global__ void ewb_kernel(const float* __restrict__ E,
                           const float* __restrict__ W,
                           const float* __restrict__ b) {
    int v = blockIdx.x, j = threadIdx.x;
    float acc = b[j];
#pragma unroll
    for (int d = 0; d < 32; d++)
        acc = fmaf(E[v * 32 + d], W[d * G4 + j], acc);
    g_EWb[v * G4 + j] = acc;
}

// ---------------- packed f32x2 helpers ----------------
__device__ __forceinline__ ull ffma2(ull a, ull b, ull c) {
    ull d;
    asm("fma.rn.f32x2 %0, %1, %2, %3;" : "=l"(d) : "l"(a), "l"(b), "l"(c));
    return d;
}
__device__ __forceinline__ ull dup2(float x) {
    ull d;
    asm("mov.b64 %0, {%1, %1};" : "=l"(d) : "f"(x));
    return d;
}
__device__ __forceinline__ ull pack2(float x, float y) {
    ull d;
    asm("mov.b64 %0, {%1, %2};" : "=l"(d) : "f"(x), "f"(y));
    return d;
}
__device__ __forceinline__ float2 unpack2(ull v) {
    float2 r;
    asm("mov.b64 {%0, %1}, %2;" : "=f"(r.x), "=f"(r.y) : "l"(v));
    return r;
}
__device__ __forceinline__ float fast_ex2(float x) {
    float y; asm("ex2.approx.f32 %0, %1;" : "=f"(y) : "f"(x)); return y;
}
__device__ __forceinline__ float fast_rcp(float x) {
    float y; asm("rcp.approx.f32 %0, %1;" : "=f"(y) : "f"(x)); return y;
}
__device__ __forceinline__ float sigmoid_(float x) {
    return fast_rcp(1.0f + fast_ex2(-1.4426950408889634f * x));
}
__device__ __forceinline__ float tanh_(float x) {
    return fmaf(-2.0f, fast_rcp(1.0f + fast_ex2(2.8853900817779268f * x)), 1.0f);
}
__device__ __forceinline__ void sts128(uint32_t addr, float x, float y, float z,
                                       float w) {
    asm volatile("st.shared.v4.f32 [%0], {%1,%2,%3,%4};"
                 :: "r"(addr), "f"(x), "f"(y), "f"(z), "f"(w) : "memory");
}
__device__ __forceinline__ uint32_t smem_u32(const void* p) {
    uint32_t a;
    asm("{ .reg .u64 t; cvta.to.shared.u64 t, %1; cvt.u32.u64 %0, t; }"
        : "=r"(a) : "l"(p));
    return a;
}
// pair-local barrier: 64 threads of one sequence group
__device__ __forceinline__ void pair_bar(int sgrp) {
    asm volatile("bar.sync %0, 64;" :: "r"(sgrp + 1) : "memory");
}

// ---------------------------------------------------------------------------
__global__ void __launch_bounds__(NTHR, 2)
lstm_kernel(const int* __restrict__ chars,
            const float* __restrict__ U,
            float* __restrict__ out) {
    extern __shared__ __align__(16) char smem[];
    const int tid  = threadIdx.x;
    const int u    = tid & 63;          // hidden unit owned by this thread
    const int sgrp = tid >> 6;          // sequence group (0..3), 8 seqs each
    const int S    = sgrp * 8;

    float4* Ug = (float4*)(smem + OFF_UG);   // Ug[k*64 + u] = {Ui,Uf,Ug,Uo}
    int*    ch = (int*)(smem + OFF_CH);

    // ---- init: rearrange U into gate-interleaved float4s ----
    for (int e = tid; e < 64 * 64; e += NTHR) {
        int k = e >> 6, uu = e & 63;
        float4 v;
        v.x = U[k * G4 +       uu];
        v.y = U[k * G4 +  64 + uu];
        v.z = U[k * G4 + 128 + uu];
        v.w = U[k * G4 + 192 + uu];
        Ug[e] = v;
    }
    // zero both h buffers (h0 = 0)
    for (uint32_t i = tid * 16; i < 2 * HBUF; i += NTHR * 16)
        *(float4*)(smem + OFF_H + i) = make_float4(0.f, 0.f, 0.f, 0.f);
    // stage chars
    for (int i = tid; i < SPB * TC; i += NTHR)
        ch[i] = chars[blockIdx.x * SPB * TC + i];
    __syncthreads();

    const uint32_t h_base = smem_u32(smem + OFF_H);

    float c_reg[8];
#pragma unroll
    for (int j = 0; j < 8; j++) c_reg[j] = 0.0f;

    for (int step = 0; step < TC; step++) {
        const int rb = step & 1;

        // ---- accumulator init: z = EWb[char] (packed over seq pairs) ----
        ull acc[16];   // acc[g*4 + p] = {z[S+2p][g*64+u], z[S+2p+1][g*64+u]}
        {
            int vv[8];
#pragma unroll
            for (int i = 0; i < 8; i++) vv[i] = ch[(S + i) * TC + step];
#pragma unroll
            for (int p = 0; p < 4; p++) {
                const float* e0 = g_EWb + vv[2 * p]     * G4 + u;
                const float* e1 = g_EWb + vv[2 * p + 1] * G4 + u;
                acc[0  + p] = pack2(e0[0],   e1[0]);
                acc[4  + p] = pack2(e0[64],  e1[64]);
                acc[8  + p] = pack2(e0[128], e1[128]);
                acc[12 + p] = pack2(e0[192], e1[192]);
            }
        }

        // ---- recurrent GEMM: z += h @ U (f32x2, 16 MACs per k) ----
        const char*   hb  = smem + OFF_H + rb * HBUF + sgrp * 32;
        const float4* ugp = Ug + u;
#pragma unroll 8
        for (int k = 0; k < 64; k++) {
            float4 ug = ugp[k * 64];
            ulonglong2 h01 = *(const ulonglong2*)(hb + k * HSTRIDE);
            ulonglong2 h23 = *(const ulonglong2*)(hb + k * HSTRIDE + 16);
            ull d;
            d = dup2(ug.x);
            acc[0]  = ffma2(h01.x, d, acc[0]);  acc[1]  = ffma2(h01.y, d, acc[1]);
            acc[2]  = ffma2(h23.x, d, acc[2]);  acc[3]  = ffma2(h23.y, d, acc[3]);
            d = dup2(ug.y);
            acc[4]  = ffma2(h01.x, d, acc[4]);  acc[5]  = ffma2(h01.y, d, acc[5]);
            acc[6]  = ffma2(h23.x, d, acc[6]);  acc[7]  = ffma2(h23.y, d, acc[7]);
            d = dup2(ug.z);
            acc[8]  = ffma2(h01.x, d, acc[8]);  acc[9]  = ffma2(h01.y, d, acc[9]);
            acc[10] = ffma2(h23.x, d, acc[10]); acc[11] = ffma2(h23.y, d, acc[11]);
            d = dup2(ug.w);
            acc[12] = ffma2(h01.x, d, acc[12]); acc[13] = ffma2(h01.y, d, acc[13]);
            acc[14] = ffma2(h23.x, d, acc[14]); acc[15] = ffma2(h23.y, d, acc[15]);
        }

        // ---- gates in registers ----
        float hv[8];
#pragma unroll
        for (int p = 0; p < 4; p++) {
            float2 zi = unpack2(acc[0  + p]);
            float2 zf = unpack2(acc[4  + p]);
            float2 zg = unpack2(acc[8  + p]);
            float2 zo = unpack2(acc[12 + p]);
            {
                float ig = sigmoid_(zi.x), fg = sigmoid_(zf.x);
                float gg = tanh_(zg.x),    og = sigmoid_(zo.x);
                float c  = fmaf(fg, c_reg[2 * p], ig * gg);
                c_reg[2 * p] = c;
                hv[2 * p] = og * tanh_(c);
            }
            {
                float ig = sigmoid_(zi.y), fg = sigmoid_(zf.y);
                float gg = tanh_(zg.y),    og = sigmoid_(zo.y);
                float c  = fmaf(fg, c_reg[2 * p + 1], ig * gg);
                c_reg[2 * p + 1] = c;
                hv[2 * p + 1] = og * tanh_(c);
            }
        }

        if (step < TC - 1) {
            // write h[u][S..S+7] as two conflict-free STS.128
            uint32_t hw = h_base + (rb ^ 1) * HBUF + u * HSTRIDE + S * 4;
            sts128(hw,      hv[0], hv[1], hv[2], hv[3]);
            sts128(hw + 16, hv[4], hv[5], hv[6], hv[7]);
            pair_bar(sgrp);   // h exchange is warp-pair-local
        } else {
            float* orow = out + (size_t)(blockIdx.x * SPB + S) * HU + u;
#pragma unroll
            for (int i = 0; i < 8; i++)
                orow[(size_t)i * HU] = hv[i];
        }
    }
}

extern "C" void kernel_launch(void* const* d_in, const int* in_sizes, int n_in,
                              void* d_out, int out_size) {
    const int*   chars = (const int*)d_in[0];
    const float* E     = (const float*)d_in[1];
    const float* W     = (const float*)d_in[2];
    const float* U     = (const float*)d_in[3];
    const float* b     = (const float*)d_in[4];
    float* out = (float*)d_out;

    cudaFuncSetAttribute(lstm_kernel,
                         cudaFuncAttributeMaxDynamicSharedMemorySize, SMEM_TOTAL);
    ewb_kernel<<<128, 256>>>(E, W, b);
    lstm_kernel<<<NBLK, NTHR, SMEM_TOTAL>>>(chars, U, out);
}